// round 1
// baseline (speedup 1.0000x reference)
#include <cuda_runtime.h>
#include <cuda_bf16.h>

#define NB 2
#define NT 2048
#define NC 1024
#define NH 16
#define ND 64
#define BAND 256

// Scratch (device globals: no allocation allowed)
__device__ float g_Q[NB * NH * NT * ND];
__device__ float g_K[NB * NH * NT * ND];
__device__ float g_V[NB * NH * NT * ND];
__device__ float g_Y[NB * NT * NC];

// ---------------------------------------------------------------------------
// SGEMM 128x128 tile, BK=8, 256 threads, 8x8 per thread (split 4+4 fragments).
// EPI==0: C scattered into g_Q/g_K/g_V ([B,H,T,D] layout). A = x.
// EPI==1: C = row-major Cmat. A = g_Y (param A ignored).
// ---------------------------------------------------------------------------
template <int EPI>
__global__ __launch_bounds__(256, 2)
void sgemm_kernel(const float* __restrict__ A,
                  const float* __restrict__ Bmat,
                  float* __restrict__ Cmat,
                  int M, int N, int K)
{
    __shared__ __align__(16) float As[8][128];
    __shared__ __align__(16) float Bs[8][128];

    const int tid = threadIdx.x;
    const int tx = tid & 15;
    const int ty = tid >> 4;
    const int bm = blockIdx.y * 128;
    const int bn = blockIdx.x * 128;

    const float* Ap = (EPI == 1) ? (const float*)g_Y : A;

    float acc[8][8];
#pragma unroll
    for (int i = 0; i < 8; i++)
#pragma unroll
        for (int j = 0; j < 8; j++) acc[i][j] = 0.f;

    const int Arow = tid >> 1, Ac4 = (tid & 1) * 4;
    const int Brow = tid >> 5, Bc4 = (tid & 31) * 4;

    const float* Aptr = Ap + (size_t)(bm + Arow) * K + Ac4;
    const float* Bptr = Bmat + (size_t)Brow * N + bn + Bc4;

    for (int k0 = 0; k0 < K; k0 += 8) {
        const float4 av = *(const float4*)(Aptr + k0);
        const float4 bv = *(const float4*)(Bptr + (size_t)k0 * N);
        __syncthreads();
        As[Ac4 + 0][Arow] = av.x;
        As[Ac4 + 1][Arow] = av.y;
        As[Ac4 + 2][Arow] = av.z;
        As[Ac4 + 3][Arow] = av.w;
        *(float4*)&Bs[Brow][Bc4] = bv;
        __syncthreads();
#pragma unroll
        for (int kk = 0; kk < 8; kk++) {
            float a[8], b[8];
            *(float4*)(a)     = *(const float4*)&As[kk][ty * 4];
            *(float4*)(a + 4) = *(const float4*)&As[kk][64 + ty * 4];
            *(float4*)(b)     = *(const float4*)&Bs[kk][tx * 4];
            *(float4*)(b + 4) = *(const float4*)&Bs[kk][64 + tx * 4];
#pragma unroll
            for (int i = 0; i < 8; i++)
#pragma unroll
                for (int j = 0; j < 8; j++)
                    acc[i][j] += a[i] * b[j];
        }
    }

#pragma unroll
    for (int i2 = 0; i2 < 2; i2++)
#pragma unroll
        for (int i = 0; i < 4; i++) {
            const int r = bm + i2 * 64 + ty * 4 + i;
#pragma unroll
            for (int j2 = 0; j2 < 2; j2++) {
                const int cb = bn + j2 * 64 + tx * 4;
                float4 v;
                v.x = acc[i2 * 4 + i][j2 * 4 + 0];
                v.y = acc[i2 * 4 + i][j2 * 4 + 1];
                v.z = acc[i2 * 4 + i][j2 * 4 + 2];
                v.w = acc[i2 * 4 + i][j2 * 4 + 3];
                if (EPI == 0) {
                    const int b = r >> 11;       // r / NT
                    const int t = r & (NT - 1);
                    const int which = cb >> 10;  // 0:q 1:k 2:v
                    const int cc = cb & (NC - 1);
                    const int h = cc >> 6;
                    const int d = cc & 63;
                    float* dst = (which == 0) ? g_Q : (which == 1) ? g_K : g_V;
                    *(float4*)&dst[(size_t)(((b * NH + h) * NT) + t) * ND + d] = v;
                } else {
                    *(float4*)&Cmat[(size_t)r * N + cb] = v;
                }
            }
        }
}

// ---------------------------------------------------------------------------
// Banded flash attention: one block per (b,h, 64-query tile). 256 threads,
// 4x4 register micro-tiles for S (64x64) and O (64x64), online softmax.
// Keys span [max(0, q0-256), q0+63] in 64-wide chunks.
// ---------------------------------------------------------------------------
__global__ __launch_bounds__(256)
void attn_kernel()
{
    extern __shared__ __align__(16) float sm[];
    float* Qs = sm;                  // [64][64]
    float* Ks = sm + 64 * 64;        // [64][65] (pad: kills 16-way conflicts)
    float* Vs = Ks + 64 * 65;        // [64][64]
    float* Ps = Vs + 64 * 64;        // [64][64]

    const int tid = threadIdx.x;
    const int tx = tid & 15;
    const int ty = tid >> 4;
    const int q0 = blockIdx.x * 64;
    const int bh = blockIdx.y;

    const float* Qg = g_Q + (size_t)bh * NT * ND;
    const float* Kg = g_K + (size_t)bh * NT * ND;
    const float* Vg = g_V + (size_t)bh * NT * ND;

    for (int i = tid; i < 64 * 16; i += 256) {
        const int r = i >> 4, d4 = (i & 15) * 4;
        *(float4*)&Qs[r * 64 + d4] = *(const float4*)&Qg[(size_t)(q0 + r) * ND + d4];
    }

    float acc[4][4];
    float mi[4], li[4];
#pragma unroll
    for (int i = 0; i < 4; i++) {
        mi[i] = -1e30f;
        li[i] = 0.f;
#pragma unroll
        for (int j = 0; j < 4; j++) acc[i][j] = 0.f;
    }

    int kstart = q0 - BAND;
    if (kstart < 0) kstart = 0;

    __syncthreads();

    for (int k0 = kstart; k0 <= q0; k0 += 64) {
        // load K (padded rows) and V tiles
        for (int i = tid; i < 64 * 16; i += 256) {
            const int r = i >> 4, d4 = (i & 15) * 4;
            const float4 kv = *(const float4*)&Kg[(size_t)(k0 + r) * ND + d4];
            Ks[r * 65 + d4 + 0] = kv.x;
            Ks[r * 65 + d4 + 1] = kv.y;
            Ks[r * 65 + d4 + 2] = kv.z;
            Ks[r * 65 + d4 + 3] = kv.w;
            *(float4*)&Vs[r * 64 + d4] = *(const float4*)&Vg[(size_t)(k0 + r) * ND + d4];
        }
        __syncthreads();

        // S = Q K^T  (4x4 per thread; rows q0+4ty+i, cols k0+4tx+j)
        float s[4][4];
#pragma unroll
        for (int i = 0; i < 4; i++)
#pragma unroll
            for (int j = 0; j < 4; j++) s[i][j] = 0.f;

#pragma unroll 8
        for (int d = 0; d < 64; d++) {
            float a[4], b[4];
#pragma unroll
            for (int i = 0; i < 4; i++) a[i] = Qs[(ty * 4 + i) * 64 + d];
#pragma unroll
            for (int j = 0; j < 4; j++) b[j] = Ks[(tx * 4 + j) * 65 + d];
#pragma unroll
            for (int i = 0; i < 4; i++)
#pragma unroll
                for (int j = 0; j < 4; j++) s[i][j] += a[i] * b[j];
        }

        // mask + online softmax. Row group = 16 lanes with equal ty (lane 0-15
        // or 16-31 of a warp), so xor-shuffles 8/4/2/1 reduce within the group.
#pragma unroll
        for (int i = 0; i < 4; i++) {
            const int q = q0 + ty * 4 + i;
            float cm = -1e30f;
#pragma unroll
            for (int j = 0; j < 4; j++) {
                const int kidx = k0 + tx * 4 + j;
                const float v =
                    (kidx <= q && kidx >= q - BAND) ? s[i][j] * 0.125f : -1e30f;
                s[i][j] = v;
                cm = fmaxf(cm, v);
            }
#pragma unroll
            for (int off = 8; off > 0; off >>= 1)
                cm = fmaxf(cm, __shfl_xor_sync(0xffffffffu, cm, off));
            const float mnew = fmaxf(mi[i], cm);
            const float alpha = __expf(mi[i] - mnew);
            float rs = 0.f;
#pragma unroll
            for (int j = 0; j < 4; j++) {
                const float p = __expf(s[i][j] - mnew);
                s[i][j] = p;
                rs += p;
            }
#pragma unroll
            for (int off = 8; off > 0; off >>= 1)
                rs += __shfl_xor_sync(0xffffffffu, rs, off);
            li[i] = li[i] * alpha + rs;
            mi[i] = mnew;
#pragma unroll
            for (int j = 0; j < 4; j++) acc[i][j] *= alpha;
            float4 pv;
            pv.x = s[i][0]; pv.y = s[i][1]; pv.z = s[i][2]; pv.w = s[i][3];
            *(float4*)&Ps[(ty * 4 + i) * 64 + tx * 4] = pv;
        }
        __syncthreads();

        // O += P V  (cols d = 4tx+j)
#pragma unroll 4
        for (int kk = 0; kk < 64; kk++) {
            float a[4];
#pragma unroll
            for (int i = 0; i < 4; i++) a[i] = Ps[(ty * 4 + i) * 64 + kk];
            const float4 bv = *(const float4*)&Vs[kk * 64 + tx * 4];
#pragma unroll
            for (int i = 0; i < 4; i++) {
                acc[i][0] += a[i] * bv.x;
                acc[i][1] += a[i] * bv.y;
                acc[i][2] += a[i] * bv.z;
                acc[i][3] += a[i] * bv.w;
            }
        }
        __syncthreads();
    }

    // normalize and write y in [B,T,C] layout for the projection GEMM
    const int b = bh >> 4;
    const int h = bh & 15;
#pragma unroll
    for (int i = 0; i < 4; i++) {
        const int t = q0 + ty * 4 + i;
        const float inv = 1.f / li[i];
        float4 v;
        v.x = acc[i][0] * inv;
        v.y = acc[i][1] * inv;
        v.z = acc[i][2] * inv;
        v.w = acc[i][3] * inv;
        *(float4*)&g_Y[(size_t)(b * NT + t) * NC + h * 64 + tx * 4] = v;
    }
}

extern "C" void kernel_launch(void* const* d_in, const int* in_sizes, int n_in,
                              void* d_out, int out_size)
{
    const float* x      = (const float*)d_in[0];
    const float* W_attn = (const float*)d_in[1];
    const float* W_proj = (const float*)d_in[2];
    float* out = (float*)d_out;

    const int smem_attn = (64 * 64 + 64 * 65 + 64 * 64 + 64 * 64) * (int)sizeof(float); // 65792 B
    cudaFuncSetAttribute(attn_kernel, cudaFuncAttributeMaxDynamicSharedMemorySize, smem_attn);

    // 1) QKV: x[4096,1024] @ W_attn[1024,3072] -> g_Q/g_K/g_V in [B,H,T,D]
    sgemm_kernel<0><<<dim3(3072 / 128, 4096 / 128), 256>>>(x, W_attn, nullptr, 4096, 3072, 1024);
    // 2) banded attention -> g_Y in [B,T,C]
    attn_kernel<<<dim3(NT / 64, NB * NH), 256, smem_attn>>>();
    // 3) proj: g_Y[4096,1024] @ W_proj[1024,1024] -> out
    sgemm_kernel<1><<<dim3(1024 / 128, 4096 / 128), 256>>>(nullptr, W_proj, out, 4096, 1024, 1024);
}